// round 1
// baseline (speedup 1.0000x reference)
#include <cuda_runtime.h>
#include <cuda_bf16.h>

#define NUM_TYPES 8
#define DIM_Q 64
#define NUM_NEURONS 64

static constexpr int W0_ELEMS = NUM_TYPES * DIM_Q * NUM_NEURONS;   // 32768
static constexpr int B0_ELEMS = NUM_TYPES * NUM_NEURONS;           // 512
static constexpr int SMEM_FLOATS = W0_ELEMS + B0_ELEMS + B0_ELEMS; // 33792
static constexpr int SMEM_BYTES = SMEM_FLOATS * 4;                 // 135168

// out = N * b1  (also initializes the poisoned output buffer)
__global__ void tnep_init_kernel(float* __restrict__ out,
                                 const float* __restrict__ b1, int n) {
    out[0] = b1[0] * (float)n;
}

__global__ __launch_bounds__(512, 1)
void tnep_kernel(const float* __restrict__ q,
                 const float* __restrict__ W0,
                 const float* __restrict__ b0,
                 const float* __restrict__ W1,
                 const int*   __restrict__ Z,
                 float* __restrict__ out,
                 int n)
{
    extern __shared__ float smem[];
    float* sW0 = smem;                  // [t][d][k] : t*4096 + d*64 + k
    float* sB0 = smem + W0_ELEMS;       // [t][k]
    float* sW1 = sB0 + B0_ELEMS;        // [t][k]

    // Cooperative weight preload (132 KB; W0 is L2-resident so this is cheap)
    for (int i = threadIdx.x; i < W0_ELEMS; i += blockDim.x) sW0[i] = W0[i];
    for (int i = threadIdx.x; i < B0_ELEMS; i += blockDim.x) sB0[i] = b0[i];
    for (int i = threadIdx.x; i < B0_ELEMS; i += blockDim.x) sW1[i] = W1[i];
    __syncthreads();

    const int lane   = threadIdx.x & 31;
    const int gwarp  = (blockIdx.x * blockDim.x + threadIdx.x) >> 5;
    const int nwarps = (gridDim.x * blockDim.x) >> 5;

    float wsum = 0.0f;

    for (int a = gwarp; a < n; a += nwarps) {
        const int z = Z[a];  // uniform across warp -> broadcast load
        const float* qa = q + (size_t)a * DIM_Q;
        const float q0 = qa[lane];        // coalesced 128B
        const float q1 = qa[lane + 32];   // coalesced 128B

        // lane owns neurons (2*lane, 2*lane+1): conflict-free LDS.64 rows
        const float* w = sW0 + z * (DIM_Q * NUM_NEURONS) + 2 * lane;
        float acc0 = sB0[z * NUM_NEURONS + 2 * lane];
        float acc1 = sB0[z * NUM_NEURONS + 2 * lane + 1];

        #pragma unroll
        for (int d = 0; d < 32; ++d) {
            const float qd = __shfl_sync(0xffffffffu, q0, d);
            const float2 wv = *reinterpret_cast<const float2*>(w + d * NUM_NEURONS);
            acc0 = fmaf(qd, wv.x, acc0);
            acc1 = fmaf(qd, wv.y, acc1);
        }
        #pragma unroll
        for (int d = 0; d < 32; ++d) {
            const float qd = __shfl_sync(0xffffffffu, q1, d);
            const float2 wv = *reinterpret_cast<const float2*>(w + (d + 32) * NUM_NEURONS);
            acc0 = fmaf(qd, wv.x, acc0);
            acc1 = fmaf(qd, wv.y, acc1);
        }

        const float h0 = tanhf(acc0);
        const float h1 = tanhf(acc1);
        wsum = fmaf(h0, sW1[z * NUM_NEURONS + 2 * lane],
               fmaf(h1, sW1[z * NUM_NEURONS + 2 * lane + 1], wsum));
    }

    // warp reduce, one atomic per warp (~2432 atomics total)
    #pragma unroll
    for (int o = 16; o > 0; o >>= 1)
        wsum += __shfl_xor_sync(0xffffffffu, wsum, o);
    if (lane == 0)
        atomicAdd(out, wsum);
}

extern "C" void kernel_launch(void* const* d_in, const int* in_sizes, int n_in,
                              void* d_out, int out_size) {
    // metadata order: descriptors, W0, b0, W1, b1, Z
    const float* q  = (const float*)d_in[0];
    const float* W0 = (const float*)d_in[1];
    const float* b0 = (const float*)d_in[2];
    const float* W1 = (const float*)d_in[3];
    const float* b1 = (const float*)d_in[4];
    const int*   Z  = (const int*)  d_in[5];
    float* out = (float*)d_out;

    const int n = in_sizes[5];  // N_ATOMS from Z length

    static bool attr_done = false;
    if (!attr_done) {
        cudaFuncSetAttribute(tnep_kernel,
                             cudaFuncAttributeMaxDynamicSharedMemorySize,
                             SMEM_BYTES);
        attr_done = true;
    }

    tnep_init_kernel<<<1, 1>>>(out, b1, n);
    tnep_kernel<<<152, 512, SMEM_BYTES>>>(q, W0, b0, W1, Z, out, n);
}